// round 16
// baseline (speedup 1.0000x reference)
#include <cuda_runtime.h>
#include <cuda_bf16.h>
#include <cstdint>

#define NN   50000
#define NE   800000
#define TE   850000   // NE + NN self loops
#define FDIM 256
#define NH   4
#define HD   64
#define NG   128
#define OD   10

// ---------------- scratch (device globals) ---------------------------------
__device__ __nv_bfloat16 g_h[NN * FDIM];     // h = in @ W (bf16 messages)
__device__ __nv_bfloat16 g_feat[NN * FDIM];  // layer output features (bf16)
__device__ float g_asrc[NN * NH];
__device__ float g_adst[NN * NH];
// CSR (built once per launch; same edges both layers)
__device__ int   g_deg[NN];
__device__ int   g_off[NN + 1];
__device__ int   g_cur[NN];
__device__ int   g_csrc[TE];

// ---------------- CSR build ------------------------------------------------
__global__ void k_count(const int* __restrict__ ei) {
    int idx = blockIdx.x * blockDim.x + threadIdx.x;
    if (idx >= TE) return;
    int d = (idx < NE) ? ei[NE + idx] : (idx - NE);
    atomicAdd(&g_deg[d], 1);
}

__global__ __launch_bounds__(1024) void k_scan() {
    const int t = threadIdx.x;
    const int CH = (NN + 1023) / 1024;   // 49
    __shared__ int sh[1024];
    int base = t * CH;
    int sum = 0;
    for (int i = 0; i < CH; i++) {
        int idx = base + i;
        if (idx < NN) sum += g_deg[idx];
    }
    sh[t] = sum;
    __syncthreads();
    for (int off = 1; off < 1024; off <<= 1) {
        int v = (t >= off) ? sh[t - off] : 0;
        __syncthreads();
        sh[t] += v;
        __syncthreads();
    }
    int run = (t == 0) ? 0 : sh[t - 1];
    for (int i = 0; i < CH; i++) {
        int idx = base + i;
        if (idx < NN) {
            g_off[idx] = run;
            g_cur[idx] = 0;
            run += g_deg[idx];
        }
    }
    if (t == 1023) g_off[NN] = sh[1023];
}

__global__ void k_scatter(const int* __restrict__ ei) {
    int idx = blockIdx.x * blockDim.x + threadIdx.x;
    if (idx >= TE) return;
    int s, d;
    if (idx < NE) { s = ei[idx]; d = ei[NE + idx]; }
    else          { s = d = idx - NE; }
    int p = g_off[d] + atomicAdd(&g_cur[d], 1);
    g_csrc[p] = s;
}

// ---------------- helpers ---------------------------------------------------
__device__ __forceinline__ uint32_t s2u(const void* p) {
    return (uint32_t)__cvta_generic_to_shared(p);
}
__device__ __forceinline__ void cpa16(uint32_t dst, const void* src) {
    asm volatile("cp.async.cg.shared.global [%0], [%1], 16;"
                 :: "r"(dst), "l"(src));
}
__device__ __forceinline__ void cpa16p(uint32_t dst, const void* src, int sz) {
    asm volatile("cp.async.cg.shared.global [%0], [%1], 16, %2;"
                 :: "r"(dst), "l"(src), "r"(sz));
}
__device__ __forceinline__ float to_tf32(float x) {
    float r;
    asm("cvt.rna.tf32.f32 %0, %1;" : "=f"(r) : "f"(x));
    return r;
}

// ---------------- tf32 GEMM + fused attention epilogue ----------------------
// Round-11 proven config (local optimum after 3 falsified variations).
#define BS_LD 136
#define B_BYTES (2 * 32 * BS_LD * 4)
#define EXTRA_BYTES ((256 + 1024) * 4)

template <typename AT>
__global__ __launch_bounds__(256, 2) void k_gemm_attn(const AT* __restrict__ A,
                                                      const float* __restrict__ B,
                                                      __nv_bfloat16* __restrict__ C,
                                                      const float* __restrict__ att_s,
                                                      const float* __restrict__ att_d,
                                                      int M) {
    constexpr bool A32 = (sizeof(AT) == 4);
    constexpr int AS_LDW = A32 ? 36 : 40;
    constexpr int A_BYTES = 2 * 128 * AS_LDW * (int)sizeof(AT);

    extern __shared__ char smc[];
    AT (*As)[128][AS_LDW] = reinterpret_cast<AT (*)[128][AS_LDW]>(smc);
    float (*Bs)[32][BS_LD] = reinterpret_cast<float (*)[32][BS_LD]>(smc + A_BYTES);
    float* satt = reinterpret_cast<float*>(smc + A_BYTES + B_BYTES);
    float* datt = satt + 128;
    float (*sps)[4] = reinterpret_cast<float (*)[4]>(datt + 128);
    float (*spd)[4] = reinterpret_cast<float (*)[4]>(datt + 128 + 512);

    const int tid = threadIdx.x;
    const int wid = tid >> 5, lane = tid & 31;
    const int warp_m = wid >> 2;
    const int warp_n = wid & 3;
    const int bm = blockIdx.x * 128;
    const int by = blockIdx.y;
    const int bn = by * 128;
    const int r = lane >> 2, c = lane & 3;

    if (tid < 128) {
        satt[tid] = att_s[by * 128 + tid];
        datt[tid] = att_d[by * 128 + tid];
    }

    float acc[4][4][4];
#pragma unroll
    for (int i = 0; i < 4; i++)
#pragma unroll
        for (int j = 0; j < 4; j++)
#pragma unroll
            for (int q = 0; q < 4; q++) acc[i][j][q] = 0.f;

    auto stage_load = [&](int st, int k0) {
        if constexpr (A32) {
#pragma unroll
            for (int i = 0; i < 4; i++) {
                int idx = tid + i * 256;
                int row = idx >> 3;
                int k4  = (idx & 7) << 2;
                cpa16p(s2u(&As[st][row][k4]), &A[(bm + row) * 256 + k0 + k4],
                       (bm + row < M) ? 16 : 0);
            }
        } else {
#pragma unroll
            for (int i = 0; i < 2; i++) {
                int idx = tid + i * 256;
                int row = idx >> 2;
                int k8  = (idx & 3) << 3;
                cpa16p(s2u(&As[st][row][k8]), &A[(bm + row) * 256 + k0 + k8],
                       (bm + row < M) ? 16 : 0);
            }
        }
#pragma unroll
        for (int i = 0; i < 4; i++) {
            int idx = tid + i * 256;
            int kk = idx >> 5;
            int n4 = (idx & 31) << 2;
            cpa16(s2u(&Bs[st][kk][n4]), &B[(k0 + kk) * 256 + bn + n4]);
        }
        asm volatile("cp.async.commit_group;");
    };

    auto afrag = [&](int cur, int m, int k) -> float {
        if constexpr (A32) return to_tf32(As[cur][m][k]);
        else               return __bfloat162float(As[cur][m][k]);
    };

    stage_load(0, 0);
    for (int t = 0; t < 8; t++) {
        const int cur = t & 1;
        if (t < 7) {
            stage_load(cur ^ 1, (t + 1) * 32);
            asm volatile("cp.async.wait_group 1;");
        } else {
            asm volatile("cp.async.wait_group 0;");
        }
        __syncthreads();
#pragma unroll
        for (int ks = 0; ks < 4; ks++) {
            const int kb = ks * 8;
            float a[4][4], b[4][2];
#pragma unroll
            for (int mt = 0; mt < 4; mt++) {
                int m0 = warp_m * 64 + mt * 16;
                a[mt][0] = afrag(cur, m0 + r, kb + c);
                a[mt][1] = afrag(cur, m0 + 8 + r, kb + c);
                a[mt][2] = afrag(cur, m0 + r, kb + 4 + c);
                a[mt][3] = afrag(cur, m0 + 8 + r, kb + 4 + c);
            }
#pragma unroll
            for (int nt = 0; nt < 4; nt++) {
                int n0 = warp_n * 32 + nt * 8;
                b[nt][0] = to_tf32(Bs[cur][kb + c][n0 + r]);
                b[nt][1] = to_tf32(Bs[cur][kb + 4 + c][n0 + r]);
            }
#pragma unroll
            for (int mt = 0; mt < 4; mt++)
#pragma unroll
                for (int nt = 0; nt < 4; nt++) {
                    asm volatile(
                        "mma.sync.aligned.m16n8k8.row.col.f32.tf32.tf32.f32 "
                        "{%0,%1,%2,%3}, {%4,%5,%6,%7}, {%8,%9}, {%0,%1,%2,%3};"
                        : "+f"(acc[mt][nt][0]), "+f"(acc[mt][nt][1]),
                          "+f"(acc[mt][nt][2]), "+f"(acc[mt][nt][3])
                        : "f"(a[mt][0]), "f"(a[mt][1]), "f"(a[mt][2]), "f"(a[mt][3]),
                          "f"(b[nt][0]), "f"(b[nt][1]));
                }
        }
        __syncthreads();
    }

    // ---- store C as bf16 ----
#pragma unroll
    for (int mt = 0; mt < 4; mt++) {
        int row0 = bm + warp_m * 64 + mt * 16 + r;
#pragma unroll
        for (int nt = 0; nt < 4; nt++) {
            int col = bn + warp_n * 32 + nt * 8 + c * 2;
            if (row0 < M)
                *(__nv_bfloat162*)&C[row0 * 256 + col] =
                    __floats2bfloat162_rn(acc[mt][nt][0], acc[mt][nt][1]);
            if (row0 + 8 < M)
                *(__nv_bfloat162*)&C[(row0 + 8) * 256 + col] =
                    __floats2bfloat162_rn(acc[mt][nt][2], acc[mt][nt][3]);
        }
    }

    // ---- fused attention epilogue (fp32 accs) ----
    float ps[8], pd[8];
#pragma unroll
    for (int mt = 0; mt < 4; mt++) {
        float s_lo = 0.f, s_hi = 0.f, d_lo = 0.f, d_hi = 0.f;
#pragma unroll
        for (int nt = 0; nt < 4; nt++) {
            int cl = warp_n * 32 + nt * 8 + c * 2;
            float w0s = satt[cl], w1s = satt[cl + 1];
            float w0d = datt[cl], w1d = datt[cl + 1];
            s_lo += acc[mt][nt][0] * w0s + acc[mt][nt][1] * w1s;
            s_hi += acc[mt][nt][2] * w0s + acc[mt][nt][3] * w1s;
            d_lo += acc[mt][nt][0] * w0d + acc[mt][nt][1] * w1d;
            d_hi += acc[mt][nt][2] * w0d + acc[mt][nt][3] * w1d;
        }
        ps[mt * 2] = s_lo; ps[mt * 2 + 1] = s_hi;
        pd[mt * 2] = d_lo; pd[mt * 2 + 1] = d_hi;
    }
#pragma unroll
    for (int i = 0; i < 8; i++) {
        ps[i] += __shfl_xor_sync(0xffffffffu, ps[i], 1);
        ps[i] += __shfl_xor_sync(0xffffffffu, ps[i], 2);
        pd[i] += __shfl_xor_sync(0xffffffffu, pd[i], 1);
        pd[i] += __shfl_xor_sync(0xffffffffu, pd[i], 2);
    }
    if (c == 0) {
#pragma unroll
        for (int mt = 0; mt < 4; mt++) {
            int rl = warp_m * 64 + mt * 16 + r;
            sps[rl][warp_n]     = ps[mt * 2];
            spd[rl][warp_n]     = pd[mt * 2];
            sps[rl + 8][warp_n] = ps[mt * 2 + 1];
            spd[rl + 8][warp_n] = pd[mt * 2 + 1];
        }
    }
    __syncthreads();
    {
        int row = tid & 127;
        int hh  = tid >> 7;
        if (bm + row < M) {
            float vs = sps[row][hh * 2] + sps[row][hh * 2 + 1];
            float vd = spd[row][hh * 2] + spd[row][hh * 2 + 1];
            g_asrc[(bm + row) * 4 + by * 2 + hh] = vs;
            g_adst[(bm + row) * 4 + by * 2 + hh] = vd;
        }
    }
}

#define GEMM_SMEM_F32  (2 * 128 * 36 * 4 + B_BYTES + EXTRA_BYTES)
#define GEMM_SMEM_BF16 (2 * 128 * 40 * 2 + B_BYTES + EXTRA_BYTES)

// ---------------- gather aggregate: 2 warps per node ------------------------
// warp = (node, half): all edges of the node, 128 of 256 feature cols.
// Per-lane segment 8B (uint2, 4 bf16); head = half*2 + (lane>>4).
// Each lane still accumulates the FULL per-head denominator (identical math).
__device__ __forceinline__ void bf4_fma(const uint2& q, float ex,
                                        float& a0, float& a1, float& a2, float& a3) {
    float2 f0 = __bfloat1622float2(*(const __nv_bfloat162*)&q.x);
    float2 f1 = __bfloat1622float2(*(const __nv_bfloat162*)&q.y);
    a0 = fmaf(f0.x, ex, a0); a1 = fmaf(f0.y, ex, a1);
    a2 = fmaf(f1.x, ex, a2); a3 = fmaf(f1.y, ex, a3);
}

__global__ __launch_bounds__(256) void k_agg(const __nv_bfloat16* __restrict__ h,
                                             const float* __restrict__ bias,
                                             __nv_bfloat16* __restrict__ feat) {
    const int gwarp = (blockIdx.x * blockDim.x + threadIdx.x) >> 5;
    const int lane  = threadIdx.x & 31;
    if (gwarp >= NN * 2) return;
    const int node = gwarp >> 1;
    const int half = gwarp & 1;
    const int beg = g_off[node], end = g_off[node + 1];
    const int hd4 = half * 2 + (lane >> 4);            // head index 0..3
    const float adh = g_adst[node * 4 + hd4];
    const int coff = half * 128 + lane * 4;            // this lane's 4 cols

    float dn = 0.f;
    float a0 = 0.f, a1 = 0.f, a2 = 0.f, a3 = 0.f;

    int j = beg;
    for (; j + 3 < end; j += 4) {
        int s0 = g_csrc[j],     s1 = g_csrc[j + 1];
        int s2 = g_csrc[j + 2], s3 = g_csrc[j + 3];
        float e0 = g_asrc[s0 * 4 + hd4] + adh;
        float e1 = g_asrc[s1 * 4 + hd4] + adh;
        float e2 = g_asrc[s2 * 4 + hd4] + adh;
        float e3 = g_asrc[s3 * 4 + hd4] + adh;
        uint2 q0 = *(const uint2*)&h[s0 * 256 + coff];
        uint2 q1 = *(const uint2*)&h[s1 * 256 + coff];
        uint2 q2 = *(const uint2*)&h[s2 * 256 + coff];
        uint2 q3 = *(const uint2*)&h[s3 * 256 + coff];
        e0 = e0 > 0.f ? e0 : 0.2f * e0;  e1 = e1 > 0.f ? e1 : 0.2f * e1;
        e2 = e2 > 0.f ? e2 : 0.2f * e2;  e3 = e3 > 0.f ? e3 : 0.2f * e3;
        float ex0 = __expf(e0), ex1 = __expf(e1);
        float ex2 = __expf(e2), ex3 = __expf(e3);
        dn += (ex0 + ex1) + (ex2 + ex3);
        bf4_fma(q0, ex0, a0, a1, a2, a3);
        bf4_fma(q1, ex1, a0, a1, a2, a3);
        bf4_fma(q2, ex2, a0, a1, a2, a3);
        bf4_fma(q3, ex3, a0, a1, a2, a3);
    }
    for (; j < end; j++) {
        int s = g_csrc[j];
        float e = g_asrc[s * 4 + hd4] + adh;
        e = e > 0.f ? e : 0.2f * e;
        float ex = __expf(e);
        uint2 q = *(const uint2*)&h[s * 256 + coff];
        dn += ex;
        bf4_fma(q, ex, a0, a1, a2, a3);
    }

    const float inv = 1.f / (dn + 1e-16f);
    float4 b0 = *(const float4*)&bias[coff];
    float o[4];
    o[0] = fmaf(a0, inv, b0.x); o[1] = fmaf(a1, inv, b0.y);
    o[2] = fmaf(a2, inv, b0.z); o[3] = fmaf(a3, inv, b0.w);
#pragma unroll
    for (int i = 0; i < 4; i++) o[i] = o[i] > 0.f ? o[i] : 0.f;
    uint2 qo;
    *(__nv_bfloat162*)&qo.x = __floats2bfloat162_rn(o[0], o[1]);
    *(__nv_bfloat162*)&qo.y = __floats2bfloat162_rn(o[2], o[3]);
    *(uint2*)&feat[node * 256 + coff] = qo;
}

// ---------------- fused pool (sorted batch) + head --------------------------
__global__ __launch_bounds__(256) void k_poolhead(const int* __restrict__ batch,
                                                  const float* __restrict__ Wf,
                                                  const float* __restrict__ bf,
                                                  float* __restrict__ out,
                                                  int out_size) {
    const int g = blockIdx.x;
    const int t = threadIdx.x;
    __shared__ int s_bnd[2];
    __shared__ float sp[256];
    if (t < 2) {
        int key = g + t;
        int lo = 0, hi = NN;
        while (lo < hi) {
            int mid = (lo + hi) >> 1;
            if (batch[mid] < key) lo = mid + 1; else hi = mid;
        }
        s_bnd[t] = lo;
    }
    __syncthreads();
    const int lo = s_bnd[0], hi = s_bnd[1];
    float s0 = 0.f, s1 = 0.f, s2 = 0.f, s3 = 0.f;
    float s4 = 0.f, s5 = 0.f, s6 = 0.f, s7 = 0.f;
    int n = lo;
    for (; n + 7 < hi; n += 8) {
        s0 += __bfloat162float(g_feat[(n + 0) * 256 + t]);
        s1 += __bfloat162float(g_feat[(n + 1) * 256 + t]);
        s2 += __bfloat162float(g_feat[(n + 2) * 256 + t]);
        s3 += __bfloat162float(g_feat[(n + 3) * 256 + t]);
        s4 += __bfloat162float(g_feat[(n + 4) * 256 + t]);
        s5 += __bfloat162float(g_feat[(n + 5) * 256 + t]);
        s6 += __bfloat162float(g_feat[(n + 6) * 256 + t]);
        s7 += __bfloat162float(g_feat[(n + 7) * 256 + t]);
    }
    for (; n < hi; n++) s0 += __bfloat162float(g_feat[n * 256 + t]);
    float cnt = (float)(hi - lo);
    cnt = cnt < 1.f ? 1.f : cnt;
    float p = (((s0 + s1) + (s2 + s3)) + ((s4 + s5) + (s6 + s7))) / cnt;
    if (out_size >= NG * OD + NG * FDIM)
        out[NG * OD + g * 256 + t] = p;
    sp[t] = p;
    __syncthreads();
    if (t < OD) {
        float s = 0.f;
        for (int c = 0; c < 256; c++) s += sp[c] * Wf[c * OD + t];
        out[g * OD + t] = s + bf[t];
    }
}

// ---------------- launch ---------------------------------------------------
extern "C" void kernel_launch(void* const* d_in, const int* in_sizes, int n_in,
                              void* d_out, int out_size) {
    const float* x     = (const float*)d_in[0];
    const int*   ei    = (const int*)d_in[1];
    const int*   batch = (const int*)d_in[3];
    const float* W1  = (const float*)d_in[4];
    const float* as1 = (const float*)d_in[5];
    const float* ad1 = (const float*)d_in[6];
    const float* b1  = (const float*)d_in[7];
    const float* W2  = (const float*)d_in[8];
    const float* as2 = (const float*)d_in[9];
    const float* ad2 = (const float*)d_in[10];
    const float* b2  = (const float*)d_in[11];
    const float* Wf  = (const float*)d_in[12];
    const float* bf  = (const float*)d_in[13];
    float* out = (float*)d_out;

    __nv_bfloat16 *p_h, *p_feat;
    int* p_deg;
    cudaGetSymbolAddress((void**)&p_h, g_h);
    cudaGetSymbolAddress((void**)&p_feat, g_feat);
    cudaGetSymbolAddress((void**)&p_deg, g_deg);

    // lazily created once (first call = correctness run, outside graph capture)
    static cudaStream_t s_side = nullptr;
    static cudaEvent_t  ev_fork = nullptr, ev_join = nullptr;
    static bool s_attr_done = false;
    if (!s_side) {
        cudaStreamCreateWithFlags(&s_side, cudaStreamNonBlocking);
        cudaEventCreateWithFlags(&ev_fork, cudaEventDisableTiming);
        cudaEventCreateWithFlags(&ev_join, cudaEventDisableTiming);
    }
    if (!s_attr_done) {
        cudaFuncSetAttribute(k_gemm_attn<float>,
                             cudaFuncAttributeMaxDynamicSharedMemorySize,
                             GEMM_SMEM_F32);
        cudaFuncSetAttribute(k_gemm_attn<__nv_bfloat16>,
                             cudaFuncAttributeMaxDynamicSharedMemorySize,
                             GEMM_SMEM_BF16);
        s_attr_done = true;
    }

    const int GEMM_MB = (NN + 127) / 128;
    const int TE_BLK  = (TE + 255) / 256;
    const int AGG_BLK = (NN * 2 + 7) / 8;    // 2 warps/node, 8 warps/block

    // ---- fork: CSR build on side stream, overlapped with layer-1 GEMM ----
    cudaEventRecord(ev_fork, 0);
    cudaStreamWaitEvent(s_side, ev_fork, 0);
    cudaMemsetAsync(p_deg, 0, NN * sizeof(int), s_side);
    k_count<<<TE_BLK, 256, 0, s_side>>>(ei);
    k_scan<<<1, 1024, 0, s_side>>>();
    k_scatter<<<TE_BLK, 256, 0, s_side>>>(ei);
    cudaEventRecord(ev_join, s_side);

    // ---- layer 1 GEMM (origin stream, concurrent with CSR build) ----
    k_gemm_attn<float><<<dim3(GEMM_MB, 2), 256, GEMM_SMEM_F32>>>(
        x, W1, p_h, as1, ad1, NN);

    // ---- join: agg needs both CSR and GEMM-1 results ----
    cudaStreamWaitEvent(0, ev_join, 0);
    k_agg<<<AGG_BLK, 256>>>(p_h, b1, p_feat);

    // ---- layer 2 ----
    k_gemm_attn<__nv_bfloat16><<<dim3(GEMM_MB, 2), 256, GEMM_SMEM_BF16>>>(
        p_feat, W2, p_h, as2, ad2, NN);
    k_agg<<<AGG_BLK, 256>>>(p_h, b2, p_feat);

    // ---- fused pool + head ----
    k_poolhead<<<NG, 256>>>(batch, Wf, bf, out, out_size);
}